// round 2
// baseline (speedup 1.0000x reference)
#include <cuda_runtime.h>
#include <cuda_bf16.h>
#include <math.h>

#define BATCH 4
#define SEQ   2048
#define HID   2048
#define INTER 5504

#define MROWS (BATCH * SEQ)           // 8192

// ---------------- scratch (device globals; no allocation) ----------------
__device__ float g_gate[(size_t)MROWS * INTER];   // gate, then reused as intermediate
__device__ float g_up  [(size_t)MROWS * INTER];
__device__ float g_s   [BATCH * INTER];           // sum over seq of inter^2

// ---------------- SGEMM: C[m,n] = sum_k A[m,K]*B[n,K]  (NT form) ----------
// A: [M,K] row-major, B: [N,K] row-major, C: [M,N] row-major.
// Tiles: BM=BN=128, BK=16, 256 threads, 8x8 register microtile.
// Requires M%128==0, N%128==0, K%16==0 (true for all three calls).
__global__ __launch_bounds__(256) void sgemm_nt(
    const float* __restrict__ A, const float* __restrict__ B,
    float* __restrict__ C, int M, int N, int K)
{
    __shared__ float As[16][128];
    __shared__ float Bs[16][128];

    const int bm = blockIdx.y * 128;
    const int bn = blockIdx.x * 128;
    const int tid = threadIdx.x;
    const int tx = tid & 15;          // 0..15 -> column group
    const int ty = tid >> 4;          // 0..15 -> row group

    float acc[8][8];
#pragma unroll
    for (int i = 0; i < 8; i++)
#pragma unroll
        for (int j = 0; j < 8; j++) acc[i][j] = 0.f;

    const int lr0 = tid >> 2;         // 0..63
    const int lk0 = (tid & 3) << 2;   // 0,4,8,12

    for (int k0 = 0; k0 < K; k0 += 16) {
#pragma unroll
        for (int i = 0; i < 2; i++) {
            const int r = lr0 + i * 64;
            float4 va = *(const float4*)(&A[(size_t)(bm + r) * K + k0 + lk0]);
            As[lk0 + 0][r] = va.x; As[lk0 + 1][r] = va.y;
            As[lk0 + 2][r] = va.z; As[lk0 + 3][r] = va.w;
            float4 vb = *(const float4*)(&B[(size_t)(bn + r) * K + k0 + lk0]);
            Bs[lk0 + 0][r] = vb.x; Bs[lk0 + 1][r] = vb.y;
            Bs[lk0 + 2][r] = vb.z; Bs[lk0 + 3][r] = vb.w;
        }
        __syncthreads();

#pragma unroll
        for (int k = 0; k < 16; k++) {
            float a[8], b[8];
            *(float4*)&a[0] = *(const float4*)&As[k][ty * 8];
            *(float4*)&a[4] = *(const float4*)&As[k][ty * 8 + 4];
            *(float4*)&b[0] = *(const float4*)&Bs[k][tx * 8];
            *(float4*)&b[4] = *(const float4*)&Bs[k][tx * 8 + 4];
#pragma unroll
            for (int i = 0; i < 8; i++)
#pragma unroll
                for (int j = 0; j < 8; j++)
                    acc[i][j] = fmaf(a[i], b[j], acc[i][j]);
        }
        __syncthreads();
    }

#pragma unroll
    for (int i = 0; i < 8; i++) {
        const size_t row = (size_t)(bm + ty * 8 + i);
        float4* cp = (float4*)&C[row * N + bn + tx * 8];
        cp[0] = make_float4(acc[i][0], acc[i][1], acc[i][2], acc[i][3]);
        cp[1] = make_float4(acc[i][4], acc[i][5], acc[i][6], acc[i][7]);
    }
}

// ---------------- zero the per-(b,i) accumulator --------------------------
__global__ void zero_s_kernel()
{
    int i = blockIdx.x * 256 + threadIdx.x;
    if (i < BATCH * INTER) g_s[i] = 0.f;
}

// ---------------- SwiGLU elementwise + seq-reduction ----------------------
// inter = silu(gate)*up, written into g_gate (reused).
// g_s[b,i] += sum over this block's seq chunk of inter^2.
// grid: (ceil(I/256), SEQ/256, BATCH), block 256; thread owns one column i.
__global__ __launch_bounds__(256) void swiglu_kernel()
{
    const int b  = blockIdx.z;
    const int i  = blockIdx.x * 256 + threadIdx.x;
    const int s0 = blockIdx.y * 256;
    if (i >= INTER) return;

    float acc = 0.f;
    for (int s = s0; s < s0 + 256; s++) {
        const size_t idx = ((size_t)b * SEQ + s) * INTER + i;
        const float gv = g_gate[idx];
        const float uv = g_up[idx];
        const float sv = gv / (1.f + expf(-gv)) * uv;  // silu(g)*u
        g_gate[idx] = sv;
        acc += sv * sv;
    }
    atomicAdd(&g_s[b * INTER + i], acc);
}

// ---------------- impacts: sqrt(s[b,i] * ||w_up[i,:]||^2) -----------------
// grid: INTER blocks of 256 threads; block reduces one w_up row.
__global__ __launch_bounds__(256) void impacts_kernel(
    const float* __restrict__ w_up, float* __restrict__ out_imp)
{
    __shared__ float red[256];
    const int i = blockIdx.x;
    float acc = 0.f;
    for (int h = threadIdx.x; h < HID; h += 256) {
        const float w = w_up[(size_t)i * HID + h];
        acc += w * w;
    }
    red[threadIdx.x] = acc;
    __syncthreads();
    for (int off = 128; off > 0; off >>= 1) {
        if (threadIdx.x < off) red[threadIdx.x] += red[threadIdx.x + off];
        __syncthreads();
    }
    if (threadIdx.x == 0) {
        const float rs = red[0];
#pragma unroll
        for (int b = 0; b < BATCH; b++)
            out_imp[b * INTER + i] = sqrtf(g_s[b * INTER + i] * rs);
    }
}

// ---------------- launch ---------------------------------------------------
extern "C" void kernel_launch(void* const* d_in, const int* in_sizes, int n_in,
                              void* d_out, int out_size)
{
    const float* x      = (const float*)d_in[0];  // [B,S,H]
    const float* w_gate = (const float*)d_in[1];  // [I,H]
    const float* w_up   = (const float*)d_in[2];  // [I,H]
    const float* w_down = (const float*)d_in[3];  // [H,I]
    float* out = (float*)d_out;                   // [B,S,H] then impacts [B,I]

    float *gate_p, *up_p;
    cudaGetSymbolAddress((void**)&gate_p, g_gate);
    cudaGetSymbolAddress((void**)&up_p,   g_up);

    // 1. zero s accumulator
    zero_s_kernel<<<(BATCH * INTER + 255) / 256, 256>>>();

    // 2. gate = x @ w_gate^T   (M=8192, N=5504, K=2048)
    {
        dim3 grid(INTER / 128, MROWS / 128);
        sgemm_nt<<<grid, 256>>>(x, w_gate, gate_p, MROWS, INTER, HID);
    }
    // 3. up = x @ w_up^T
    {
        dim3 grid(INTER / 128, MROWS / 128);
        sgemm_nt<<<grid, 256>>>(x, w_up, up_p, MROWS, INTER, HID);
    }
    // 4. inter = silu(gate)*up (into g_gate), accumulate g_s
    {
        dim3 grid((INTER + 255) / 256, SEQ / 256, BATCH);
        swiglu_kernel<<<grid, 256>>>();
    }
    // 5. out = inter @ w_down^T  (M=8192, N=2048, K=5504)
    {
        dim3 grid(HID / 128, MROWS / 128);
        sgemm_nt<<<grid, 256>>>(gate_p, w_down, out, MROWS, HID, INTER);
    }
    // 6. impacts -> out + B*S*H
    impacts_kernel<<<INTER, 256>>>(w_up, out + (size_t)MROWS * HID);
}

// round 4
// speedup vs baseline: 3.1362x; 3.1362x over previous
#include <cuda_runtime.h>
#include <cuda_bf16.h>
#include <math.h>
#include <stdint.h>

#define BATCH 4
#define SEQ   2048
#define HID   2048
#define INTER 5504
#define MROWS (BATCH * SEQ)            // 8192

// ---------------------------------------------------------------------------
// Scratch (device globals; no allocation allowed)
// ---------------------------------------------------------------------------
__device__ __nv_bfloat16 g_xh[(size_t)MROWS * HID];
__device__ __nv_bfloat16 g_xl[(size_t)MROWS * HID];
__device__ __nv_bfloat16 g_wgh[(size_t)INTER * HID];
__device__ __nv_bfloat16 g_wgl[(size_t)INTER * HID];
__device__ __nv_bfloat16 g_wuh[(size_t)INTER * HID];
__device__ __nv_bfloat16 g_wul[(size_t)INTER * HID];
__device__ __nv_bfloat16 g_wdh[(size_t)HID * INTER];
__device__ __nv_bfloat16 g_wdl[(size_t)HID * INTER];
__device__ float g_gate[(size_t)MROWS * INTER];
__device__ float g_up  [(size_t)MROWS * INTER];
__device__ __nv_bfloat16 g_ih[(size_t)MROWS * INTER];
__device__ __nv_bfloat16 g_il[(size_t)MROWS * INTER];
__device__ float g_s[BATCH * INTER];

// ---------------------------------------------------------------------------
// PTX helpers (sm_80-class only: cp.async + ldmatrix + mma.sync)
// ---------------------------------------------------------------------------
__device__ __forceinline__ uint32_t smem_u32(const void* p) {
    uint32_t a;
    asm("{ .reg .u64 t; cvta.to.shared.u64 t, %1; cvt.u32.u64 %0, t; }"
        : "=r"(a) : "l"(p));
    return a;
}

#define SWZ(o) ((o) ^ (((o) >> 3) & 0x70))

__device__ __forceinline__ void cp16(uint32_t s, const void* g) {
    asm volatile("cp.async.cg.shared.global [%0], [%1], 16;" :: "r"(s), "l"(g));
}
__device__ __forceinline__ void cp_commit() {
    asm volatile("cp.async.commit_group;" ::: "memory");
}
template <int N>
__device__ __forceinline__ void cp_wait() {
    asm volatile("cp.async.wait_group %0;" :: "n"(N) : "memory");
}

__device__ __forceinline__ void ldmx4(uint32_t* d, uint32_t addr) {
    asm volatile("ldmatrix.sync.aligned.m8n8.x4.shared.b16 {%0,%1,%2,%3}, [%4];"
                 : "=r"(d[0]), "=r"(d[1]), "=r"(d[2]), "=r"(d[3]) : "r"(addr));
}

__device__ __forceinline__ void mma_bf16(float* c, const uint32_t* a,
                                         const uint32_t* b) {
    asm volatile(
        "mma.sync.aligned.m16n8k16.row.col.f32.bf16.bf16.f32 "
        "{%0,%1,%2,%3}, {%4,%5,%6,%7}, {%8,%9}, {%0,%1,%2,%3};"
        : "+f"(c[0]), "+f"(c[1]), "+f"(c[2]), "+f"(c[3])
        : "r"(a[0]), "r"(a[1]), "r"(a[2]), "r"(a[3]), "r"(b[0]), "r"(b[1]));
}

// ---------------------------------------------------------------------------
// HMMA bf16 split GEMM: C[m,n] = sum_k A[m,k]*B[n,k]  (NT, K-major both)
// A = Ahi+Alo, B = Bhi+Blo; 3-term accumulation (hh, hl, lh).
// CTA tile 128x128, BK=64, 3-stage cp.async, 512 thr (16 warps, 32x32 each).
// Requires M%128==0, N%128==0, K%64==0, K/64 >= 3.
// ---------------------------------------------------------------------------
#define STAGES 3
#define TILE_B 16384            // one 128x64 bf16 tile (SW128 swizzled)
#define STAGE_B (4 * TILE_B)    // Ahi, Alo, Bhi, Blo
#define GEMM_SMEM (STAGES * STAGE_B)    // 196608

__device__ __forceinline__ void load_stage(
    uint32_t stage_base,
    const __nv_bfloat16* __restrict__ Ahi, const __nv_bfloat16* __restrict__ Alo,
    const __nv_bfloat16* __restrict__ Bhi, const __nv_bfloat16* __restrict__ Blo,
    int K, int bm, int bn, int k0, int tid)
{
#pragma unroll
    for (int it = 0; it < 2; it++) {
        const int idx = tid + it * 512;          // 0..1023
        const int r = idx >> 3;                  // row 0..127
        const int c = idx & 7;                   // 16B chunk 0..7
        const uint32_t so = SWZ((uint32_t)(r * 128 + c * 16));
        const size_t ga = (size_t)(bm + r) * K + k0 + c * 8;
        const size_t gb = (size_t)(bn + r) * K + k0 + c * 8;
        cp16(stage_base + so,              Ahi + ga);
        cp16(stage_base + TILE_B + so,     Alo + ga);
        cp16(stage_base + 2 * TILE_B + so, Bhi + gb);
        cp16(stage_base + 3 * TILE_B + so, Blo + gb);
    }
}

__global__ __launch_bounds__(512, 1) void gemm_bf16x3(
    const __nv_bfloat16* __restrict__ Ahi, const __nv_bfloat16* __restrict__ Alo,
    const __nv_bfloat16* __restrict__ Bhi, const __nv_bfloat16* __restrict__ Blo,
    float* __restrict__ C, int N, int K)
{
    extern __shared__ char smem[];
    const uint32_t sb = smem_u32(smem);
    const int tid  = threadIdx.x;
    const int wid  = tid >> 5;
    const int lane = tid & 31;
    const int bm = blockIdx.y * 128;
    const int bn = blockIdx.x * 128;
    const int KT = K >> 6;

    const int m0 = (wid & 3) * 32;     // warp row offset within CTA tile
    const int n0 = (wid >> 2) * 32;    // warp col offset

    float acc[2][4][4];
#pragma unroll
    for (int mt = 0; mt < 2; mt++)
#pragma unroll
        for (int nt = 0; nt < 4; nt++)
#pragma unroll
            for (int j = 0; j < 4; j++) acc[mt][nt][j] = 0.f;

    // prologue: stages 0 and 1 in flight
    load_stage(sb, Ahi, Alo, Bhi, Blo, K, bm, bn, 0, tid);
    cp_commit();
    load_stage(sb + STAGE_B, Ahi, Alo, Bhi, Blo, K, bm, bn, 64, tid);
    cp_commit();

    // ldmatrix lane addressing (constant per thread)
    const int arow = lane & 15;            // A: rows m0..m0+15
    const int ak   = lane >> 4;            // A: k-chunk select (0/1)
    const int brow = (lane & 7) + ((lane >> 4) & 1) * 8;  // B: n row
    const int bk   = (lane >> 3) & 1;      // B: k-chunk select

    for (int i = 0; i < KT; i++) {
        cp_wait<1>();
        __syncthreads();

        // prefetch stage i+2 into the slot consumed at iter i-1
        if (i + 2 < KT)
            load_stage(sb + ((i + 2) % STAGES) * STAGE_B, Ahi, Alo, Bhi, Blo,
                       K, bm, bn, (i + 2) * 64, tid);
        cp_commit();   // uniform group accounting (possibly empty)

        const uint32_t s0 = sb + (i % STAGES) * STAGE_B;
#pragma unroll
        for (int k = 0; k < 4; k++) {
            uint32_t ah[2][4], al[2][4], bh[4][2], bl[4][2];
#pragma unroll
            for (int mt = 0; mt < 2; mt++) {
                const uint32_t off =
                    SWZ((uint32_t)((m0 + mt * 16 + arow) * 128 + (2 * k + ak) * 16));
                ldmx4(ah[mt], s0 + off);
                ldmx4(al[mt], s0 + TILE_B + off);
            }
#pragma unroll
            for (int np = 0; np < 2; np++) {
                const uint32_t off =
                    SWZ((uint32_t)((n0 + np * 16 + brow) * 128 + (2 * k + bk) * 16));
                uint32_t q[4];
                ldmx4(q, s0 + 2 * TILE_B + off);
                bh[2 * np][0] = q[0]; bh[2 * np][1] = q[1];
                bh[2 * np + 1][0] = q[2]; bh[2 * np + 1][1] = q[3];
                ldmx4(q, s0 + 3 * TILE_B + off);
                bl[2 * np][0] = q[0]; bl[2 * np][1] = q[1];
                bl[2 * np + 1][0] = q[2]; bl[2 * np + 1][1] = q[3];
            }
#pragma unroll
            for (int mt = 0; mt < 2; mt++)
#pragma unroll
                for (int nt = 0; nt < 4; nt++) {
                    mma_bf16(acc[mt][nt], ah[mt], bh[nt]);
                    mma_bf16(acc[mt][nt], ah[mt], bl[nt]);
                    mma_bf16(acc[mt][nt], al[mt], bh[nt]);
                }
        }
    }

    // epilogue: write 32x32 warp tile
#pragma unroll
    for (int mt = 0; mt < 2; mt++) {
        const int row = bm + m0 + mt * 16 + (lane >> 2);
#pragma unroll
        for (int nt = 0; nt < 4; nt++) {
            const int col = bn + n0 + nt * 8 + (lane & 3) * 2;
            float2* p0 = (float2*)&C[(size_t)row * N + col];
            float2* p1 = (float2*)&C[(size_t)(row + 8) * N + col];
            *p0 = make_float2(acc[mt][nt][0], acc[mt][nt][1]);
            *p1 = make_float2(acc[mt][nt][2], acc[mt][nt][3]);
        }
    }
}

// ---------------------------------------------------------------------------
// fp32 -> bf16 hi/lo split
// ---------------------------------------------------------------------------
__global__ __launch_bounds__(256) void split_kernel(
    const float* __restrict__ in, __nv_bfloat16* __restrict__ hi,
    __nv_bfloat16* __restrict__ lo, int n4)
{
    const int i = blockIdx.x * 256 + threadIdx.x;
    if (i >= n4) return;
    const float4 v = ((const float4*)in)[i];
    __nv_bfloat16 h0 = __float2bfloat16(v.x);
    __nv_bfloat16 h1 = __float2bfloat16(v.y);
    __nv_bfloat16 h2 = __float2bfloat16(v.z);
    __nv_bfloat16 h3 = __float2bfloat16(v.w);
    __nv_bfloat16 l0 = __float2bfloat16(v.x - __bfloat162float(h0));
    __nv_bfloat16 l1 = __float2bfloat16(v.y - __bfloat162float(h1));
    __nv_bfloat16 l2 = __float2bfloat16(v.z - __bfloat162float(h2));
    __nv_bfloat16 l3 = __float2bfloat16(v.w - __bfloat162float(h3));
    __nv_bfloat162* hp = (__nv_bfloat162*)(hi + (size_t)i * 4);
    __nv_bfloat162* lp = (__nv_bfloat162*)(lo + (size_t)i * 4);
    hp[0] = __nv_bfloat162(h0, h1);
    hp[1] = __nv_bfloat162(h2, h3);
    lp[0] = __nv_bfloat162(l0, l1);
    lp[1] = __nv_bfloat162(l2, l3);
}

// ---------------------------------------------------------------------------
__global__ void zero_s_kernel()
{
    int i = blockIdx.x * 256 + threadIdx.x;
    if (i < BATCH * INTER) g_s[i] = 0.f;
}

// ---------------------------------------------------------------------------
// SwiGLU: inter = silu(gate)*up -> bf16 hi/lo, accumulate s = sum_seq inter^2
// ---------------------------------------------------------------------------
__global__ __launch_bounds__(256) void swiglu_kernel()
{
    const int b = blockIdx.z;
    const int i4 = (blockIdx.x * 256 + threadIdx.x) * 4;
    const int s0 = blockIdx.y * 128;
    if (i4 >= INTER) return;

    float a0 = 0.f, a1 = 0.f, a2 = 0.f, a3 = 0.f;
    for (int s = s0; s < s0 + 128; s++) {
        const size_t idx = ((size_t)b * SEQ + s) * INTER + i4;
        const float4 g = *(const float4*)(g_gate + idx);
        const float4 u = *(const float4*)(g_up + idx);
        const float v0 = g.x / (1.f + expf(-g.x)) * u.x;
        const float v1 = g.y / (1.f + expf(-g.y)) * u.y;
        const float v2 = g.z / (1.f + expf(-g.z)) * u.z;
        const float v3 = g.w / (1.f + expf(-g.w)) * u.w;
        a0 += v0 * v0; a1 += v1 * v1; a2 += v2 * v2; a3 += v3 * v3;
        __nv_bfloat16 h0 = __float2bfloat16(v0);
        __nv_bfloat16 h1 = __float2bfloat16(v1);
        __nv_bfloat16 h2 = __float2bfloat16(v2);
        __nv_bfloat16 h3 = __float2bfloat16(v3);
        __nv_bfloat162* hp = (__nv_bfloat162*)(g_ih + idx);
        hp[0] = __nv_bfloat162(h0, h1);
        hp[1] = __nv_bfloat162(h2, h3);
        __nv_bfloat16 l0 = __float2bfloat16(v0 - __bfloat162float(h0));
        __nv_bfloat16 l1 = __float2bfloat16(v1 - __bfloat162float(h1));
        __nv_bfloat16 l2 = __float2bfloat16(v2 - __bfloat162float(h2));
        __nv_bfloat16 l3 = __float2bfloat16(v3 - __bfloat162float(h3));
        __nv_bfloat162* lp = (__nv_bfloat162*)(g_il + idx);
        lp[0] = __nv_bfloat162(l0, l1);
        lp[1] = __nv_bfloat162(l2, l3);
    }
    atomicAdd(&g_s[b * INTER + i4 + 0], a0);
    atomicAdd(&g_s[b * INTER + i4 + 1], a1);
    atomicAdd(&g_s[b * INTER + i4 + 2], a2);
    atomicAdd(&g_s[b * INTER + i4 + 3], a3);
}

// ---------------------------------------------------------------------------
__global__ __launch_bounds__(256) void impacts_kernel(
    const float* __restrict__ w_up, float* __restrict__ out_imp)
{
    __shared__ float red[256];
    const int i = blockIdx.x;
    float acc = 0.f;
    for (int h = threadIdx.x; h < HID; h += 256) {
        const float w = w_up[(size_t)i * HID + h];
        acc += w * w;
    }
    red[threadIdx.x] = acc;
    __syncthreads();
    for (int off = 128; off > 0; off >>= 1) {
        if (threadIdx.x < off) red[threadIdx.x] += red[threadIdx.x + off];
        __syncthreads();
    }
    if (threadIdx.x == 0) {
        const float rs = red[0];
#pragma unroll
        for (int b = 0; b < BATCH; b++)
            out_imp[b * INTER + i] = sqrtf(g_s[b * INTER + i] * rs);
    }
}

// ---------------------------------------------------------------------------
extern "C" void kernel_launch(void* const* d_in, const int* in_sizes, int n_in,
                              void* d_out, int out_size)
{
    const float* x      = (const float*)d_in[0];
    const float* w_gate = (const float*)d_in[1];
    const float* w_up   = (const float*)d_in[2];
    const float* w_down = (const float*)d_in[3];
    float* out = (float*)d_out;

    __nv_bfloat16 *xh, *xl, *wgh, *wgl, *wuh, *wul, *wdh, *wdl, *ih, *il;
    float *gate, *up;
    cudaGetSymbolAddress((void**)&xh, g_xh);
    cudaGetSymbolAddress((void**)&xl, g_xl);
    cudaGetSymbolAddress((void**)&wgh, g_wgh);
    cudaGetSymbolAddress((void**)&wgl, g_wgl);
    cudaGetSymbolAddress((void**)&wuh, g_wuh);
    cudaGetSymbolAddress((void**)&wul, g_wul);
    cudaGetSymbolAddress((void**)&wdh, g_wdh);
    cudaGetSymbolAddress((void**)&wdl, g_wdl);
    cudaGetSymbolAddress((void**)&ih, g_ih);
    cudaGetSymbolAddress((void**)&il, g_il);
    cudaGetSymbolAddress((void**)&gate, g_gate);
    cudaGetSymbolAddress((void**)&up, g_up);

    cudaFuncSetAttribute(gemm_bf16x3,
                         cudaFuncAttributeMaxDynamicSharedMemorySize, GEMM_SMEM);

    zero_s_kernel<<<(BATCH * INTER + 255) / 256, 256>>>();

    {
        const int nx4 = MROWS * HID / 4;
        split_kernel<<<(nx4 + 255) / 256, 256>>>(x, xh, xl, nx4);
        const int nw4 = INTER * HID / 4;
        split_kernel<<<(nw4 + 255) / 256, 256>>>(w_gate, wgh, wgl, nw4);
        split_kernel<<<(nw4 + 255) / 256, 256>>>(w_up, wuh, wul, nw4);
        split_kernel<<<(nw4 + 255) / 256, 256>>>(w_down, wdh, wdl, nw4);
    }

    // gate = x @ w_gate^T ; up = x @ w_up^T   (M=8192, N=5504, K=2048)
    {
        dim3 grid(INTER / 128, MROWS / 128);
        gemm_bf16x3<<<grid, 512, GEMM_SMEM>>>(xh, xl, wgh, wgl, gate, INTER, HID);
        gemm_bf16x3<<<grid, 512, GEMM_SMEM>>>(xh, xl, wuh, wul, up, INTER, HID);
    }

    // inter = silu(gate)*up -> bf16 hi/lo ; s accumulation
    {
        dim3 grid((INTER / 4 + 255) / 256, 16, BATCH);
        swiglu_kernel<<<grid, 256>>>();
    }

    // out = inter @ w_down^T  (M=8192, N=2048, K=5504)
    {
        dim3 grid(HID / 128, MROWS / 128);
        gemm_bf16x3<<<grid, 512, GEMM_SMEM>>>(ih, il, wdh, wdl, out, HID, INTER);
    }

    impacts_kernel<<<INTER, 256>>>(w_up, out + (size_t)MROWS * HID);
}